// round 3
// baseline (speedup 1.0000x reference)
#include <cuda_runtime.h>

#define BDIM 8
#define CDIM 64
#define NDIM 256
#define FDIM 128
#define EPS 1e-5f
#define NCHUNK 4
#define ROWS_PER_CHUNK (NDIM / NCHUNK)   // 64

// Scratch (allocation-free rule: __device__ globals)
__device__ unsigned char g_mask[BDIM * CDIM * NDIM];
__device__ float  g_psupp[BDIM * CDIM * NCHUNK * FDIM];
__device__ float  g_pquery[BDIM * CDIM * NCHUNK * FDIM];
__device__ float  g_psq [BDIM * CDIM * NCHUNK * 2];       // [ssq_supp, ssq_query]
__device__ float  g_S1[BDIM * CDIM];
__device__ float  g_S2[BDIM * CDIM];
__device__ float2 g_wgt[BDIM * CDIM];                     // (w0, w1)
__device__ float2 g_scale[BDIM * CDIM];                   // (w0*gr, w1*gr)
__device__ float  g_shift[BDIM * CDIM];                   // beta - mean*gr

__device__ __forceinline__ float warpsum(float v) {
#pragma unroll
    for (int o = 16; o; o >>= 1) v += __shfl_xor_sync(0xffffffffu, v, o);
    return v;
}

// ---------------------------------------------------------------------------
// Kernel 1: reduction pass. 4 CTAs per (b,c), 64 rows each, warp-per-row,
// two rows in flight per warp per iteration (R1-proven structure).
// ---------------------------------------------------------------------------
__global__ void __launch_bounds__(256, 6) k1(const float* __restrict__ h,
                                             const float* __restrict__ op) {
    const int bc    = blockIdx.x >> 2;
    const int chunk = blockIdx.x & 3;
    const int c     = bc & (CDIM - 1);
    const int tid   = threadIdx.x;
    const int w     = tid >> 5, lane = tid & 31;

    const float* hbase = h + (size_t)bc * NDIM * FDIM;
    const float4* op4 = (const float4*)(op + c * 2 * FDIM);
    const float4 olo = op4[lane];       // op[c][0:128]   (source part)
    const float4 ohi = op4[32 + lane];  // op[c][128:256] (h part)

    // s_lo = dot(source, op_lo), redundant per warp/block (L1/L2-hot)
    const float4 s0 = ((const float4*)hbase)[lane];
    const float s_lo = warpsum(s0.x * olo.x + s0.y * olo.y + s0.z * olo.z + s0.w * olo.w);

    __shared__ float s_supp[FDIM];
    __shared__ float s_query[FDIM];
    __shared__ float s_sq[2];
    if (tid < FDIM) { s_supp[tid] = 0.f; s_query[tid] = 0.f; }
    if (tid < 2) s_sq[tid] = 0.f;
    __syncthreads();

    float4 sp = {0.f, 0.f, 0.f, 0.f}, qr = {0.f, 0.f, 0.f, 0.f};
    float ssq = 0.f, qsq = 0.f;

    const int base = chunk * ROWS_PER_CHUNK;
#pragma unroll
    for (int i = 0; i < 4; i++) {
        const int n0 = base + w + i * 16;
        const int n1 = n0 + 8;
        const float4 hv0 = ((const float4*)(hbase + (size_t)n0 * FDIM))[lane];
        const float4 hv1 = ((const float4*)(hbase + (size_t)n1 * FDIM))[lane];

        float a0 = warpsum(hv0.x * ohi.x + hv0.y * ohi.y + hv0.z * ohi.z + hv0.w * ohi.w);
        float a1 = warpsum(hv1.x * ohi.x + hv1.y * ohi.y + hv1.z * ohi.z + hv1.w * ohi.w);
        const bool m0 = (s_lo + a0) >= 0.f;
        const bool m1 = (s_lo + a1) >= 0.f;
        const float d0 = hv0.x * hv0.x + hv0.y * hv0.y + hv0.z * hv0.z + hv0.w * hv0.w;
        const float d1 = hv1.x * hv1.x + hv1.y * hv1.y + hv1.z * hv1.z + hv1.w * hv1.w;

        if (m0) { sp.x += hv0.x; sp.y += hv0.y; sp.z += hv0.z; sp.w += hv0.w; ssq += d0; }
        else    { qr.x += hv0.x; qr.y += hv0.y; qr.z += hv0.z; qr.w += hv0.w; qsq += d0; }
        if (m1) { sp.x += hv1.x; sp.y += hv1.y; sp.z += hv1.z; sp.w += hv1.w; ssq += d1; }
        else    { qr.x += hv1.x; qr.y += hv1.y; qr.z += hv1.z; qr.w += hv1.w; qsq += d1; }

        if (lane == 0) {
            g_mask[bc * NDIM + n0] = m0 ? 1 : 0;
            g_mask[bc * NDIM + n1] = m1 ? 1 : 0;
        }
    }

    // Fold per-lane vector partials into smem (128 distinct addresses/warp)
    atomicAdd(&s_supp[lane * 4 + 0], sp.x);
    atomicAdd(&s_supp[lane * 4 + 1], sp.y);
    atomicAdd(&s_supp[lane * 4 + 2], sp.z);
    atomicAdd(&s_supp[lane * 4 + 3], sp.w);
    atomicAdd(&s_query[lane * 4 + 0], qr.x);
    atomicAdd(&s_query[lane * 4 + 1], qr.y);
    atomicAdd(&s_query[lane * 4 + 2], qr.z);
    atomicAdd(&s_query[lane * 4 + 3], qr.w);
    ssq = warpsum(ssq);
    qsq = warpsum(qsq);
    if (lane == 0) { atomicAdd(&s_sq[0], ssq); atomicAdd(&s_sq[1], qsq); }
    __syncthreads();

    if (tid < FDIM) {
        g_psupp [(size_t)blockIdx.x * FDIM + tid] = s_supp[tid];
        g_pquery[(size_t)blockIdx.x * FDIM + tid] = s_query[tid];
    }
    if (tid < 2) g_psq[blockIdx.x * 2 + tid] = s_sq[tid];
}

// ---------------------------------------------------------------------------
// Kernel 2: one warp per (b,c). Fold 4 chunk partials, opS/opQ dots,
// softmax weights, BN partial sums.
// ---------------------------------------------------------------------------
__global__ __launch_bounds__(256) void k2(const float* __restrict__ h,
                                          const float* __restrict__ opS,
                                          const float* __restrict__ opQ) {
    const int bc   = blockIdx.x * 8 + (threadIdx.x >> 5);
    const int c    = bc & (CDIM - 1);
    const int lane = threadIdx.x & 31;

    float4 sp = {0.f, 0.f, 0.f, 0.f}, qm = {0.f, 0.f, 0.f, 0.f};
#pragma unroll
    for (int k = 0; k < NCHUNK; k++) {
        const float4 a = ((const float4*)(g_psupp  + (size_t)(bc * NCHUNK + k) * FDIM))[lane];
        const float4 b = ((const float4*)(g_pquery + (size_t)(bc * NCHUNK + k) * FDIM))[lane];
        sp.x += a.x; sp.y += a.y; sp.z += a.z; sp.w += a.w;
        qm.x += b.x; qm.y += b.y; qm.z += b.z; qm.w += b.w;
    }

    const float4 src = ((const float4*)(h + (size_t)bc * NDIM * FDIM))[lane];
    const float4 oS0 = ((const float4*)(opS + c * 2 * FDIM))[lane];
    const float4 oS1 = ((const float4*)(opS + c * 2 * FDIM + FDIM))[lane];
    const float4 oQ0 = ((const float4*)(opQ + c * 2 * FDIM))[lane];
    const float4 oQ1 = ((const float4*)(opQ + c * 2 * FDIM + FDIM))[lane];

    const float invN = 1.f / (float)NDIM;
    float tS = (sp.x * oS0.x + sp.y * oS0.y + sp.z * oS0.z + sp.w * oS0.w) * invN
             + (src.x * oS1.x + src.y * oS1.y + src.z * oS1.z + src.w * oS1.w);
    float tQ = (qm.x * oQ0.x + qm.y * oQ0.y + qm.z * oQ0.z + qm.w * oQ0.w) * invN
             + (src.x * oQ1.x + src.y * oQ1.y + src.z * oQ1.z + src.w * oQ1.w);
    float sumS = sp.x + sp.y + sp.z + sp.w;
    float sumQ = qm.x + qm.y + qm.z + qm.w;

    tS = warpsum(tS);
    tQ = warpsum(tQ);
    sumS = warpsum(sumS);
    sumQ = warpsum(sumQ);

    if (lane == 0) {
        const float mx = fmaxf(tS, tQ);
        const float e0 = expf(tS - mx), e1 = expf(tQ - mx);
        const float inv = 1.f / (e0 + e1);
        const float w0 = e0 * inv, w1 = e1 * inv;
        g_wgt[bc] = make_float2(w0, w1);
        float sqS = 0.f, sqQ = 0.f;
#pragma unroll
        for (int k = 0; k < NCHUNK; k++) {
            sqS += g_psq[(bc * NCHUNK + k) * 2 + 0];
            sqQ += g_psq[(bc * NCHUNK + k) * 2 + 1];
        }
        g_S1[bc] = w0 * sumS + w1 * sumQ;
        g_S2[bc] = w0 * w0 * sqS + w1 * w1 * sqQ;
    }
}

// ---------------------------------------------------------------------------
// Kernel 2b: per-channel stats, then per-(b,c) scale/shift. One 512-thr block.
// ---------------------------------------------------------------------------
__global__ __launch_bounds__(512) void k2b(const float* __restrict__ gamma,
                                           const float* __restrict__ beta) {
    __shared__ float2 s_stat[CDIM];
    const int t = threadIdx.x;
    if (t < CDIM) {
        float s1 = 0.f, s2 = 0.f;
#pragma unroll
        for (int b = 0; b < BDIM; b++) {
            s1 += g_S1[b * CDIM + t];
            s2 += g_S2[b * CDIM + t];
        }
        const float inv = 1.f / (float)(BDIM * NDIM * FDIM);
        const float mean = s1 * inv;
        const float var = s2 * inv - mean * mean;
        s_stat[t] = make_float2(mean, rsqrtf(var + EPS));
    }
    __syncthreads();
    const int bc = t;  // 512 = BDIM*CDIM
    const int c = bc & (CDIM - 1);
    const float2 st = s_stat[c];
    const float gr = gamma[c] * st.y;
    const float2 wv = g_wgt[bc];
    g_scale[bc] = make_float2(wv.x * gr, wv.y * gr);
    g_shift[bc] = beta[c] - st.x * gr;
}

// ---------------------------------------------------------------------------
// Kernel 3: streaming elementwise: elu(h*scale + shift)
// ---------------------------------------------------------------------------
__global__ __launch_bounds__(256) void k3(const float* __restrict__ h,
                                          float* __restrict__ out) {
    const int i = blockIdx.x * blockDim.x + threadIdx.x;  // float4 index
    const int bc = i >> 13;                               // 8192 float4 per (b,c)
    const unsigned char m = g_mask[i >> 5];               // uniform per warp
    const float2 sc = g_scale[bc];
    const float scale = m ? sc.x : sc.y;
    const float shift = g_shift[bc];

    const float4 hv = ((const float4*)h)[i];
    float4 y;
    y.x = hv.x * scale + shift;
    y.y = hv.y * scale + shift;
    y.z = hv.z * scale + shift;
    y.w = hv.w * scale + shift;
    y.x = (y.x > 0.f) ? y.x : (__expf(y.x) - 1.f);
    y.y = (y.y > 0.f) ? y.y : (__expf(y.y) - 1.f);
    y.z = (y.z > 0.f) ? y.z : (__expf(y.z) - 1.f);
    y.w = (y.w > 0.f) ? y.w : (__expf(y.w) - 1.f);
    ((float4*)out)[i] = y;
}

extern "C" void kernel_launch(void* const* d_in, const int* in_sizes, int n_in,
                              void* d_out, int out_size) {
    const float* h     = (const float*)d_in[0];
    const float* op    = (const float*)d_in[1];
    const float* opS   = (const float*)d_in[2];
    const float* opQ   = (const float*)d_in[3];
    const float* gamma = (const float*)d_in[4];
    const float* beta  = (const float*)d_in[5];
    float* out = (float*)d_out;

    k1<<<BDIM * CDIM * NCHUNK, 256>>>(h, op);
    k2<<<BDIM * CDIM / 8, 256>>>(h, opS, opQ);
    k2b<<<1, 512>>>(gamma, beta);
    const int total4 = (BDIM * CDIM * NDIM * FDIM) / 4;  // 4,194,304
    k3<<<total4 / 256, 256>>>(h, out);
}

// round 4
// speedup vs baseline: 1.7068x; 1.7068x over previous
#include <cuda_runtime.h>

#define BDIM 8
#define CDIM 64
#define NDIM 256
#define FDIM 128
#define EPS 1e-5f

// Scratch (allocation-free rule: __device__ globals)
__device__ unsigned char g_mask[BDIM * CDIM * NDIM];
__device__ float  g_S1[BDIM * CDIM];
__device__ float  g_S2[BDIM * CDIM];
__device__ float2 g_wgt[BDIM * CDIM];     // (w0, w1)
__device__ float2 g_scale[BDIM * CDIM];   // (w0*gr, w1*gr)
__device__ float  g_shift[BDIM * CDIM];   // beta - mean*gr

__device__ __forceinline__ float warpsum(float v) {
#pragma unroll
    for (int o = 16; o; o >>= 1) v += __shfl_xor_sync(0xffffffffu, v, o);
    return v;
}

// ---------------------------------------------------------------------------
// Kernel 1: one CTA per (b,c), 384 threads (12 warps). Warp-per-row, two
// independent rows in flight per iteration (rows n0 and n0+128). Inline
// epilogue computes opS/opQ dots, softmax weights, BN partial sums.
// All 512 CTAs resident in a single wave (4 blocks/SM x 148 SMs >= 512).
// ---------------------------------------------------------------------------
__global__ void __launch_bounds__(384) k1(const float* __restrict__ h,
                                          const float* __restrict__ op,
                                          const float* __restrict__ opS,
                                          const float* __restrict__ opQ) {
    const int bc  = blockIdx.x;
    const int c   = bc & (CDIM - 1);
    const int tid = threadIdx.x;
    const int w   = tid >> 5, lane = tid & 31;

    const float* hbase = h + (size_t)bc * NDIM * FDIM;
    const float4* op4 = (const float4*)(op + c * 2 * FDIM);
    const float4 olo = op4[lane];       // op[c][0:128]   (source part)
    const float4 ohi = op4[32 + lane];  // op[c][128:256] (h part)

    // s_lo = dot(source, op_lo), redundant per warp (source row is L1-hot)
    const float4 s0 = ((const float4*)hbase)[lane];
    const float s_lo = warpsum(s0.x * olo.x + s0.y * olo.y + s0.z * olo.z + s0.w * olo.w);

    __shared__ float s_supp[FDIM];
    __shared__ float s_query[FDIM];
    __shared__ float acc[6];  // [ssqS, ssqQ, tS, tQ, sumS, sumQ]
    if (tid < FDIM) { s_supp[tid] = 0.f; s_query[tid] = 0.f; }
    if (tid < 6) acc[tid] = 0.f;
    __syncthreads();

    float4 sp = {0.f, 0.f, 0.f, 0.f}, qr = {0.f, 0.f, 0.f, 0.f};
    float ssq = 0.f, qsq = 0.f;

    // Warp w handles row pairs (n0, n0+128) for n0 = w, w+12, ... < 128.
    for (int n0 = w; n0 < NDIM / 2; n0 += 12) {
        const int n1 = n0 + NDIM / 2;
        const float4 hv0 = ((const float4*)(hbase + (size_t)n0 * FDIM))[lane];
        const float4 hv1 = ((const float4*)(hbase + (size_t)n1 * FDIM))[lane];

        float a0 = warpsum(hv0.x * ohi.x + hv0.y * ohi.y + hv0.z * ohi.z + hv0.w * ohi.w);
        float a1 = warpsum(hv1.x * ohi.x + hv1.y * ohi.y + hv1.z * ohi.z + hv1.w * ohi.w);
        const bool m0 = (s_lo + a0) >= 0.f;
        const bool m1 = (s_lo + a1) >= 0.f;
        const float d0 = hv0.x * hv0.x + hv0.y * hv0.y + hv0.z * hv0.z + hv0.w * hv0.w;
        const float d1 = hv1.x * hv1.x + hv1.y * hv1.y + hv1.z * hv1.z + hv1.w * hv1.w;

        if (m0) { sp.x += hv0.x; sp.y += hv0.y; sp.z += hv0.z; sp.w += hv0.w; ssq += d0; }
        else    { qr.x += hv0.x; qr.y += hv0.y; qr.z += hv0.z; qr.w += hv0.w; qsq += d0; }
        if (m1) { sp.x += hv1.x; sp.y += hv1.y; sp.z += hv1.z; sp.w += hv1.w; ssq += d1; }
        else    { qr.x += hv1.x; qr.y += hv1.y; qr.z += hv1.z; qr.w += hv1.w; qsq += d1; }

        if (lane == 0) {
            g_mask[bc * NDIM + n0] = m0 ? 1 : 0;
            g_mask[bc * NDIM + n1] = m1 ? 1 : 0;
        }
    }

    // Fold per-lane vector partials into smem (128 distinct addresses/warp)
    atomicAdd(&s_supp[lane * 4 + 0], sp.x);
    atomicAdd(&s_supp[lane * 4 + 1], sp.y);
    atomicAdd(&s_supp[lane * 4 + 2], sp.z);
    atomicAdd(&s_supp[lane * 4 + 3], sp.w);
    atomicAdd(&s_query[lane * 4 + 0], qr.x);
    atomicAdd(&s_query[lane * 4 + 1], qr.y);
    atomicAdd(&s_query[lane * 4 + 2], qr.z);
    atomicAdd(&s_query[lane * 4 + 3], qr.w);
    ssq = warpsum(ssq);
    qsq = warpsum(qsq);
    if (lane == 0) { atomicAdd(&acc[0], ssq); atomicAdd(&acc[1], qsq); }
    __syncthreads();

    // Epilogue: supp_attn / query_attn scalars and vector-sum totals
    if (tid < FDIM) {
        const int f = tid;
        const float src = hbase[f];
        const float fs = s_supp[f];
        const float fq = s_query[f];
        float tS = (fs * (1.f / NDIM)) * opS[c * 2 * FDIM + f] + src * opS[c * 2 * FDIM + FDIM + f];
        float tQ = (fq * (1.f / NDIM)) * opQ[c * 2 * FDIM + f] + src * opQ[c * 2 * FDIM + FDIM + f];
        float rS = warpsum(tS);
        float rQ = warpsum(tQ);
        float rfs = warpsum(fs);
        float rfq = warpsum(fq);
        if (lane == 0) {
            atomicAdd(&acc[2], rS);
            atomicAdd(&acc[3], rQ);
            atomicAdd(&acc[4], rfs);
            atomicAdd(&acc[5], rfq);
        }
    }
    __syncthreads();

    if (tid == 0) {
        const float sa = acc[2], qa = acc[3];
        const float mx = fmaxf(sa, qa);
        const float e0 = expf(sa - mx), e1 = expf(qa - mx);
        const float inv = 1.f / (e0 + e1);
        const float w0 = e0 * inv, w1 = e1 * inv;
        g_wgt[bc] = make_float2(w0, w1);
        g_S1[bc] = w0 * acc[4] + w1 * acc[5];
        g_S2[bc] = w0 * w0 * acc[0] + w1 * w1 * acc[1];
    }
}

// ---------------------------------------------------------------------------
// Kernel 2: per-channel stats, then per-(b,c) scale/shift. One 512-thr block.
// ---------------------------------------------------------------------------
__global__ __launch_bounds__(512) void k2(const float* __restrict__ gamma,
                                          const float* __restrict__ beta) {
    __shared__ float2 s_stat[CDIM];
    const int t = threadIdx.x;
    if (t < CDIM) {
        float s1 = 0.f, s2 = 0.f;
#pragma unroll
        for (int b = 0; b < BDIM; b++) {
            s1 += g_S1[b * CDIM + t];
            s2 += g_S2[b * CDIM + t];
        }
        const float inv = 1.f / (float)(BDIM * NDIM * FDIM);
        const float mean = s1 * inv;
        const float var = s2 * inv - mean * mean;
        s_stat[t] = make_float2(mean, rsqrtf(var + EPS));
    }
    __syncthreads();
    const int bc = t;  // 512 = BDIM*CDIM
    const int c = bc & (CDIM - 1);
    const float2 st = s_stat[c];
    const float gr = gamma[c] * st.y;
    const float2 wv = g_wgt[bc];
    g_scale[bc] = make_float2(wv.x * gr, wv.y * gr);
    g_shift[bc] = beta[c] - st.x * gr;
}

// ---------------------------------------------------------------------------
// Kernel 3: streaming elementwise: elu(h*scale + shift)
// ---------------------------------------------------------------------------
__global__ __launch_bounds__(256) void k3(const float* __restrict__ h,
                                          float* __restrict__ out) {
    const int i = blockIdx.x * blockDim.x + threadIdx.x;  // float4 index
    const int bc = i >> 13;                               // 8192 float4 per (b,c)
    const unsigned char m = g_mask[i >> 5];               // uniform per warp (one row per warp)
    const float2 sc = g_scale[bc];
    const float scale = m ? sc.x : sc.y;
    const float shift = g_shift[bc];

    const float4 hv = ((const float4*)h)[i];
    float4 y;
    y.x = hv.x * scale + shift;
    y.y = hv.y * scale + shift;
    y.z = hv.z * scale + shift;
    y.w = hv.w * scale + shift;
    y.x = (y.x > 0.f) ? y.x : (__expf(y.x) - 1.f);
    y.y = (y.y > 0.f) ? y.y : (__expf(y.y) - 1.f);
    y.z = (y.z > 0.f) ? y.z : (__expf(y.z) - 1.f);
    y.w = (y.w > 0.f) ? y.w : (__expf(y.w) - 1.f);
    ((float4*)out)[i] = y;
}

extern "C" void kernel_launch(void* const* d_in, const int* in_sizes, int n_in,
                              void* d_out, int out_size) {
    const float* h     = (const float*)d_in[0];
    const float* op    = (const float*)d_in[1];
    const float* opS   = (const float*)d_in[2];
    const float* opQ   = (const float*)d_in[3];
    const float* gamma = (const float*)d_in[4];
    const float* beta  = (const float*)d_in[5];
    float* out = (float*)d_out;

    k1<<<BDIM * CDIM, 384>>>(h, op, opS, opQ);
    k2<<<1, 512>>>(gamma, beta);
    const int total4 = (BDIM * CDIM * NDIM * FDIM) / 4;  // 4,194,304
    k3<<<total4 / 256, 256>>>(h, out);
}

// round 6
// speedup vs baseline: 1.7952x; 1.0518x over previous
#include <cuda_runtime.h>

#define BDIM 8
#define CDIM 64
#define NDIM 256
#define FDIM 128
#define EPS 1e-5f

// Scratch (allocation-free rule: __device__ globals)
__device__ unsigned char g_mask[BDIM * CDIM * NDIM];
__device__ float  g_S1[BDIM * CDIM];
__device__ float  g_S2[BDIM * CDIM];
__device__ float2 g_wgt[BDIM * CDIM];     // (w0, w1)
__device__ float2 g_scale[BDIM * CDIM];   // (w0*gr, w1*gr)
__device__ float  g_shift[BDIM * CDIM];   // beta - mean*gr

__device__ __forceinline__ float warpsum(float v) {
#pragma unroll
    for (int o = 16; o; o >>= 1) v += __shfl_xor_sync(0xffffffffu, v, o);
    return v;
}

__device__ __forceinline__ float dot4(float4 a, float4 b) {
    return a.x * b.x + a.y * b.y + a.z * b.z + a.w * b.w;
}

// ---------------------------------------------------------------------------
// Kernel 1: one CTA per (b,c), 256 threads (8 warps), 4 rows per warp per
// iteration (4 interleaved butterfly chains). Scalarized accumulators via
// linearity: only 7 per-lane scalars survive the loop; one reduce at the end.
// 4 CTAs/SM -> all 512 CTAs resident in a single wave.
// ---------------------------------------------------------------------------
__global__ void __launch_bounds__(256, 4) k1(const float* __restrict__ h,
                                             const float* __restrict__ op,
                                             const float* __restrict__ opS,
                                             const float* __restrict__ opQ) {
    const int bc  = blockIdx.x;
    const int c   = bc & (CDIM - 1);
    const int tid = threadIdx.x;
    const int w   = tid >> 5, lane = tid & 31;

    const float* hbase = h + (size_t)bc * NDIM * FDIM;
    const float4* op4  = (const float4*)(op  + c * 2 * FDIM);
    const float4* opS4 = (const float4*)(opS + c * 2 * FDIM);
    const float4* opQ4 = (const float4*)(opQ + c * 2 * FDIM);
    const float4 ohi  = op4[32 + lane];   // op[c][128:256] (h part)
    const float4 oSlo = opS4[lane];       // opS[c][0:128]  (mean part)
    const float4 oQlo = opQ4[lane];       // opQ[c][0:128]  (mean part)

    // s_lo = dot(source, op_lo) (source row is L1-hot; once per warp)
    const float4 s0 = ((const float4*)hbase)[lane];
    const float s_lo = warpsum(dot4(s0, op4[lane]));

    __shared__ float accs[7];  // [dS_s, dQ_t, dQ_s, sm_t, sm_s, sq_t, sq_s]
    if (tid < 7) accs[tid] = 0.f;
    __syncthreads();

    float a_dSs = 0.f, a_dQt = 0.f, a_dQs = 0.f;
    float a_smt = 0.f, a_sms = 0.f, a_sqt = 0.f, a_sqs = 0.f;

    // Warp w handles rows n0 = it*32 + w*4 .. +3  (8 iterations)
#pragma unroll 2
    for (int it = 0; it < 8; it++) {
        const int n0 = it * 32 + w * 4;
        const float4* r = (const float4*)(hbase + (size_t)n0 * FDIM);
        const float4 v0 = r[lane];
        const float4 v1 = r[32 + lane];
        const float4 v2 = r[64 + lane];
        const float4 v3 = r[96 + lane];

        float p0 = dot4(v0, ohi);
        float p1 = dot4(v1, ohi);
        float p2 = dot4(v2, ohi);
        float p3 = dot4(v3, ohi);
        // 4 interleaved butterfly chains
#pragma unroll
        for (int o = 16; o; o >>= 1) {
            p0 += __shfl_xor_sync(0xffffffffu, p0, o);
            p1 += __shfl_xor_sync(0xffffffffu, p1, o);
            p2 += __shfl_xor_sync(0xffffffffu, p2, o);
            p3 += __shfl_xor_sync(0xffffffffu, p3, o);
        }
        const float m0 = (s_lo + p0) >= 0.f ? 1.f : 0.f;
        const float m1 = (s_lo + p1) >= 0.f ? 1.f : 0.f;
        const float m2 = (s_lo + p2) >= 0.f ? 1.f : 0.f;
        const float m3 = (s_lo + p3) >= 0.f ? 1.f : 0.f;
        if (lane == 0) {
            uchar4 mk;
            mk.x = (unsigned char)m0; mk.y = (unsigned char)m1;
            mk.z = (unsigned char)m2; mk.w = (unsigned char)m3;
            *(uchar4*)(g_mask + bc * NDIM + n0) = mk;
        }

        // Per-row scalar partials; tot-accums have no mask dependency.
        {
            float pS = dot4(v0, oSlo); a_dSs = fmaf(m0, pS, a_dSs);
            float pQ = dot4(v0, oQlo); a_dQt += pQ; a_dQs = fmaf(m0, pQ, a_dQs);
            float ps = v0.x + v0.y + v0.z + v0.w; a_smt += ps; a_sms = fmaf(m0, ps, a_sms);
            float pq = dot4(v0, v0); a_sqt += pq; a_sqs = fmaf(m0, pq, a_sqs);
        }
        {
            float pS = dot4(v1, oSlo); a_dSs = fmaf(m1, pS, a_dSs);
            float pQ = dot4(v1, oQlo); a_dQt += pQ; a_dQs = fmaf(m1, pQ, a_dQs);
            float ps = v1.x + v1.y + v1.z + v1.w; a_smt += ps; a_sms = fmaf(m1, ps, a_sms);
            float pq = dot4(v1, v1); a_sqt += pq; a_sqs = fmaf(m1, pq, a_sqs);
        }
        {
            float pS = dot4(v2, oSlo); a_dSs = fmaf(m2, pS, a_dSs);
            float pQ = dot4(v2, oQlo); a_dQt += pQ; a_dQs = fmaf(m2, pQ, a_dQs);
            float ps = v2.x + v2.y + v2.z + v2.w; a_smt += ps; a_sms = fmaf(m2, ps, a_sms);
            float pq = dot4(v2, v2); a_sqt += pq; a_sqs = fmaf(m2, pq, a_sqs);
        }
        {
            float pS = dot4(v3, oSlo); a_dSs = fmaf(m3, pS, a_dSs);
            float pQ = dot4(v3, oQlo); a_dQt += pQ; a_dQs = fmaf(m3, pQ, a_dQs);
            float ps = v3.x + v3.y + v3.z + v3.w; a_smt += ps; a_sms = fmaf(m3, ps, a_sms);
            float pq = dot4(v3, v3); a_sqt += pq; a_sqs = fmaf(m3, pq, a_sqs);
        }
    }

    // Fold the 7 per-lane accumulators (interleaved butterflies), then smem.
#pragma unroll
    for (int o = 16; o; o >>= 1) {
        a_dSs += __shfl_xor_sync(0xffffffffu, a_dSs, o);
        a_dQt += __shfl_xor_sync(0xffffffffu, a_dQt, o);
        a_dQs += __shfl_xor_sync(0xffffffffu, a_dQs, o);
        a_smt += __shfl_xor_sync(0xffffffffu, a_smt, o);
        a_sms += __shfl_xor_sync(0xffffffffu, a_sms, o);
        a_sqt += __shfl_xor_sync(0xffffffffu, a_sqt, o);
        a_sqs += __shfl_xor_sync(0xffffffffu, a_sqs, o);
    }
    if (lane == 0) {
        atomicAdd(&accs[0], a_dSs);
        atomicAdd(&accs[1], a_dQt);
        atomicAdd(&accs[2], a_dQs);
        atomicAdd(&accs[3], a_smt);
        atomicAdd(&accs[4], a_sms);
        atomicAdd(&accs[5], a_sqt);
        atomicAdd(&accs[6], a_sqs);
    }
    __syncthreads();

    // Epilogue (warp 0): source dots with opS_hi/opQ_hi, softmax, BN partials
    if (tid < 32) {
        const float4 oShi = opS4[32 + lane];
        const float4 oQhi = opQ4[32 + lane];
        float tSrcS = dot4(s0, oShi);
        float tSrcQ = dot4(s0, oQhi);
#pragma unroll
        for (int o = 16; o; o >>= 1) {
            tSrcS += __shfl_xor_sync(0xffffffffu, tSrcS, o);
            tSrcQ += __shfl_xor_sync(0xffffffffu, tSrcQ, o);
        }
        if (lane == 0) {
            const float tS = accs[0] * (1.f / NDIM) + tSrcS;
            const float tQ = (accs[1] - accs[2]) * (1.f / NDIM) + tSrcQ;
            const float mx = fmaxf(tS, tQ);
            const float e0 = expf(tS - mx), e1 = expf(tQ - mx);
            const float inv = 1.f / (e0 + e1);
            const float w0 = e0 * inv, w1 = e1 * inv;
            g_wgt[bc] = make_float2(w0, w1);
            g_S1[bc] = w0 * accs[4] + w1 * (accs[3] - accs[4]);
            g_S2[bc] = w0 * w0 * accs[6] + w1 * w1 * (accs[5] - accs[6]);
        }
    }
}

// ---------------------------------------------------------------------------
// Kernel 2: per-channel stats, then per-(b,c) scale/shift. One 512-thr block.
// ---------------------------------------------------------------------------
__global__ __launch_bounds__(512) void k2(const float* __restrict__ gamma,
                                          const float* __restrict__ beta) {
    __shared__ float2 s_stat[CDIM];
    const int t = threadIdx.x;
    if (t < CDIM) {
        float s1 = 0.f, s2 = 0.f;
#pragma unroll
        for (int b = 0; b < BDIM; b++) {
            s1 += g_S1[b * CDIM + t];
            s2 += g_S2[b * CDIM + t];
        }
        const float inv = 1.f / (float)(BDIM * NDIM * FDIM);
        const float mean = s1 * inv;
        const float var = s2 * inv - mean * mean;
        s_stat[t] = make_float2(mean, rsqrtf(var + EPS));
    }
    __syncthreads();
    const int bc = t;  // 512 = BDIM*CDIM
    const int c = bc & (CDIM - 1);
    const float2 st = s_stat[c];
    const float gr = gamma[c] * st.y;
    const float2 wv = g_wgt[bc];
    g_scale[bc] = make_float2(wv.x * gr, wv.y * gr);
    g_shift[bc] = beta[c] - st.x * gr;
}

// ---------------------------------------------------------------------------
// Kernel 3: streaming elementwise: elu(h*scale + shift)
// ---------------------------------------------------------------------------
__global__ __launch_bounds__(256) void k3(const float* __restrict__ h,
                                          float* __restrict__ out) {
    const int i = blockIdx.x * blockDim.x + threadIdx.x;  // float4 index
    const int bc = i >> 13;                               // 8192 float4 per (b,c)
    const unsigned char m = g_mask[i >> 5];               // uniform per warp
    const float2 sc = g_scale[bc];
    const float scale = m ? sc.x : sc.y;
    const float shift = g_shift[bc];

    const float4 hv = ((const float4*)h)[i];
    float4 y;
    y.x = hv.x * scale + shift;
    y.y = hv.y * scale + shift;
    y.z = hv.z * scale + shift;
    y.w = hv.w * scale + shift;
    y.x = (y.x > 0.f) ? y.x : (__expf(y.x) - 1.f);
    y.y = (y.y > 0.f) ? y.y : (__expf(y.y) - 1.f);
    y.z = (y.z > 0.f) ? y.z : (__expf(y.z) - 1.f);
    y.w = (y.w > 0.f) ? y.w : (__expf(y.w) - 1.f);
    ((float4*)out)[i] = y;
}

extern "C" void kernel_launch(void* const* d_in, const int* in_sizes, int n_in,
                              void* d_out, int out_size) {
    const float* h     = (const float*)d_in[0];
    const float* op    = (const float*)d_in[1];
    const float* opS   = (const float*)d_in[2];
    const float* opQ   = (const float*)d_in[3];
    const float* gamma = (const float*)d_in[4];
    const float* beta  = (const float*)d_in[5];
    float* out = (float*)d_out;

    k1<<<BDIM * CDIM, 256>>>(h, op, opS, opQ);
    k2<<<1, 512>>>(gamma, beta);
    const int total4 = (BDIM * CDIM * NDIM * FDIM) / 4;  // 4,194,304
    k3<<<total4 / 256, 256>>>(h, out);
}